// round 14
// baseline (speedup 1.0000x reference)
#include <cuda_runtime.h>
#include <cuda_bf16.h>
#include <stdint.h>

#define NB 16
#define NN 8192
#define NE 262144
#define ND 8
#define NC 128               // NB*ND columns of the transposed H matrix
#define WPR 256              // words per bitmap row = NN/32
#define NCHG 256             // global 32-k chunks
#define HTILE 8192           // per-half per-gc B tile bytes (4 sl x 4 np x 32 lanes x 16B)
#define ONE_BF16X2 0x3F803F80u

// k_pse dispatch
#define TRANS_CTAS 4096      // NN*NC/256
#define MAKEB_CTAS 2048      // 2^19/256
#define PREP_CTAS  (TRANS_CTAS + MAKEB_CTAS)
#define SE_CTAS    32768     // 16384 scatter + 16384 edge, parity-interleaved
#define PSE_CTAS   (PREP_CTAS + SE_CTAS)

// k_md dispatch
#define MMA_CTAS   128       // 64 mtiles x 2 n-halves, full K each
#define DEG_CTAS   128

// ---------------- device scratch (no allocs allowed) ----------------
__device__ uint32_t g_bits[NN * WPR];            // 8 MB adjacency bitmap
__device__ float    g_inv_deg[NN];
__device__ float    g_Ht[NN * NC];               // 4 MB
__device__ uint8_t  g_Bf[2 * NCHG * HTILE];      // 4 MB: [half][gc][8KB tile]
__device__ int      g_is64;
__device__ int      g_deg_done;

// ---------------- PTX helpers ----------------
__device__ __forceinline__ void mbar_init(uint32_t mbar, uint32_t count) {
    asm volatile("mbarrier.init.shared.b64 [%0], %1;" :: "r"(mbar), "r"(count) : "memory");
}
__device__ __forceinline__ void mbar_expect_tx(uint32_t mbar, uint32_t bytes) {
    asm volatile("mbarrier.arrive.expect_tx.shared.b64 _, [%0], %1;"
                 :: "r"(mbar), "r"(bytes) : "memory");
}
__device__ __forceinline__ void bulk_g2s(uint32_t dst, const void* src, uint32_t bytes, uint32_t mbar) {
    asm volatile("cp.async.bulk.shared::cluster.global.mbarrier::complete_tx::bytes [%0], [%1], %2, [%3];"
                 :: "r"(dst), "l"(src), "r"(bytes), "r"(mbar) : "memory");
}
__device__ __forceinline__ void mbar_wait(uint32_t mbar, uint32_t parity) {
    asm volatile(
        "{\n\t.reg .pred P;\n\t"
        "WAIT_%=:\n\t"
        "mbarrier.try_wait.parity.acquire.cta.shared::cta.b64 P, [%0], %1, 0x989680;\n\t"
        "@!P bra WAIT_%=;\n\t}"
        :: "r"(mbar), "r"(parity) : "memory");
}
__device__ __forceinline__ void mma_bf16(float* c, const uint32_t* a, uint32_t b0, uint32_t b1) {
    asm("mma.sync.aligned.m16n8k16.row.col.f32.bf16.bf16.f32 "
        "{%0,%1,%2,%3}, {%4,%5,%6,%7}, {%8,%9}, {%0,%1,%2,%3};"
        : "+f"(c[0]), "+f"(c[1]), "+f"(c[2]), "+f"(c[3])
        : "r"(a[0]), "r"(a[1]), "r"(a[2]), "r"(a[3]), "r"(b0), "r"(b1));
}
__device__ __forceinline__ int load_idx(const void* p, long long e, bool is64) {
    return is64 ? (int)((const long long*)p)[e] : ((const int*)p)[e];
}

// ---------------- init: clear bitmap + detect + reset counter ----------------
__global__ __launch_bounds__(256) void k_init(const void* adj_i) {
    int idx = blockIdx.x * 256 + threadIdx.x;
    ((uint4*)g_bits)[idx] = make_uint4(0u, 0u, 0u, 0u);
    if (idx == 0) {
        const int* p = (const int*)adj_i;
        int odd_nonzero = 0;
        #pragma unroll
        for (int t = 0; t < 32; t++)
            if (p[2 * t + 1] != 0) odd_nonzero = 1;
        g_is64 = odd_nonzero ? 0 : 1;
        g_deg_done = 0;
    }
}

// ---------------- pse: transpose + makeB + scatter + edge (fused) ----------------
__global__ __launch_bounds__(256) void k_pse(
        const float* __restrict__ h,
        const void* adj_i, const void* adj_j,
        const float* __restrict__ W, const float* __restrict__ bias,
        float* __restrict__ edge_out) {
    int bid = blockIdx.x;
    int t   = threadIdx.x;

    if (bid < TRANS_CTAS) {
        int idx = bid * 256 + t;                   // over NN*NC
        int k = idx >> 7;
        int c = idx & 127;
        int b = c >> 3, d = c & 7;
        g_Ht[idx] = h[((long long)b * NN + k) * ND + d];
        return;
    }
    if (bid < PREP_CTAS) {
        int idx = (bid - TRANS_CTAS) * 256 + t;    // 2^19
        int lane = idx & 31;
        int nb   = (idx >> 5) & 15;
        int sl   = (idx >> 9) & 3;
        int gc   = idx >> 11;
        int tg = lane & 3, g = lane >> 2;
        int n  = nb * 8 + g;
        int kb = gc * 32 + sl * 8;
        int b = n >> 3, d = n & 7;
        float v0 = h[((long long)b * NN + (kb + tg)) * ND + d];
        float v1 = h[((long long)b * NN + (kb + 4 + tg)) * ND + d];
        __nv_bfloat16 h0 = __float2bfloat16(v0);
        __nv_bfloat16 l0 = __float2bfloat16(v0 - __bfloat162float(h0));
        __nv_bfloat16 h1 = __float2bfloat16(v1);
        __nv_bfloat16 l1 = __float2bfloat16(v1 - __bfloat162float(h1));
        uint32_t r0 = (uint32_t)__bfloat16_as_ushort(h0) | ((uint32_t)__bfloat16_as_ushort(l0) << 16);
        uint32_t r1 = (uint32_t)__bfloat16_as_ushort(h1) | ((uint32_t)__bfloat16_as_ushort(l1) << 16);
        int half = nb >> 3, nbl = nb & 7;
        uint2* dst = (uint2*)(g_Bf + (size_t)half * (NCHG * HTILE) + (size_t)gc * HTILE
                              + sl * 2048 + (nbl >> 1) * 512 + lane * 16 + (nbl & 1) * 8);
        *dst = make_uint2(r0, r1);
        return;
    }

    int r = bid - PREP_CTAS;
    bool is64 = g_is64;
    if (r & 1) {
        // ---- scatter ----
        long long idx = (long long)(r >> 1) * 256 + t;
        int i = load_idx(adj_i, idx, is64);
        int j = load_idx(adj_j, idx, is64);
        atomicOr(&g_bits[i * WPR + (j >> 5)], 1u << (j & 31));
        atomicOr(&g_bits[j * WPR + (i >> 5)], 1u << (i & 31));
    } else {
        // ---- edge_out ----
        __shared__ float sW[64];
        __shared__ float sb[8];
        if (t < 64) sW[t] = W[t];
        if (t < 8)  sb[t] = bias[t];
        __syncthreads();

        long long idx = (long long)(r >> 1) * 256 + t;
        int bb = (int)(idx >> 18);
        int e  = (int)(idx & (NE - 1));
        int i = load_idx(adj_i, e, is64);   // batch-0 indices only
        int j = load_idx(adj_j, e, is64);

        const float4* h4 = (const float4*)h;
        long long bi = ((long long)bb * NN + i) * 2;
        long long bj = ((long long)bb * NN + j) * 2;
        float4 x0 = h4[bi], x1 = h4[bi + 1];
        float4 y0 = h4[bj], y1 = h4[bj + 1];
        float s[8] = {x0.x + y0.x, x0.y + y0.y, x0.z + y0.z, x0.w + y0.w,
                      x1.x + y1.x, x1.y + y1.y, x1.z + y1.z, x1.w + y1.w};
        float o[8];
        #pragma unroll
        for (int d = 0; d < 8; d++) {
            float a2 = sb[d];
            #pragma unroll
            for (int k = 0; k < 8; k++) a2 += s[k] * sW[d * 8 + k];
            o[d] = a2;
        }
        float4* out4 = (float4*)(edge_out + idx * 8);
        out4[0] = make_float4(o[0], o[1], o[2], o[3]);
        out4[1] = make_float4(o[4], o[5], o[6], o[7]);
    }
}

// ---------------- md: N-split full-K MMA GEMM + degree, fused epilogue ----------------
// bids [0,128):   MMA, CTA = 128 rows x 64 cols (half hf), full K. No partials:
//                 epilogue spin-waits on deg counter, writes final new_h.
// bids [128,256): degree -> inv_deg, then counter arrive.
__global__ __launch_bounds__(256) void k_md(float* __restrict__ new_h) {
    __shared__ __align__(1024) uint8_t sB[2][2 * HTILE];     // 32 KB
    __shared__ __align__(8) unsigned long long smbar[2];

    int bid  = blockIdx.x;
    int t    = threadIdx.x;
    int lane = t & 31;
    int w    = t >> 5;

    if (bid < MMA_CTAS) {
        int wr = w >> 1;                 // m-row 0..3
        int wc = w & 1;                  // n-col 0..1 (32 cols each within the 64-col half)
        int tg = lane & 3, g = lane >> 2;

        int hf    = bid & 1;
        int mtile = bid >> 1;
        int rowbase = mtile * 128 + wr * 32;

        const uint32_t* __restrict__ bits = g_bits;
        const uint8_t*  __restrict__ Bsrc = g_Bf + (size_t)hf * (NCHG * HTILE);

        uint32_t mb  = (uint32_t)__cvta_generic_to_shared(&smbar[0]);
        uint32_t sb0 = (uint32_t)__cvta_generic_to_shared(&sB[0][0]);

        if (t == 0) {
            mbar_init(mb, 1);
            mbar_init(mb + 8, 1);
            asm volatile("fence.proxy.async.shared::cta;" ::: "memory");
        }
        __syncthreads();
        if (t == 0) {
            mbar_expect_tx(mb, 2 * HTILE);
            bulk_g2s(sb0, Bsrc, 2 * HTILE, mb);
            mbar_expect_tx(mb + 8, 2 * HTILE);
            bulk_g2s(sb0 + 2 * HTILE, Bsrc + 2 * HTILE, 2 * HTILE, mb + 8);
        }

        float acc[2][4][4];
        #pragma unroll
        for (int mt = 0; mt < 2; mt++)
            #pragma unroll
            for (int ni = 0; ni < 4; ni++)
                #pragma unroll
                for (int rr = 0; rr < 4; rr++) acc[mt][ni][rr] = 0.0f;

        for (int cc = 0; cc < NCHG / 2; cc++) {      // 128 iters, 2 gc each
            int buf = cc & 1;
            mbar_wait(mb + buf * 8, (cc >> 1) & 1);

            #pragma unroll
            for (int sub = 0; sub < 2; sub++) {
                uint32_t wrd = __ldg(&bits[(rowbase + lane) * WPR + cc * 2 + sub]);
                uint32_t wA0 = __shfl_sync(0xffffffffu, wrd, g);
                uint32_t wA1 = __shfl_sync(0xffffffffu, wrd, g + 8);
                uint32_t wA2 = __shfl_sync(0xffffffffu, wrd, g + 16);
                uint32_t wA3 = __shfl_sync(0xffffffffu, wrd, g + 24);

                const uint8_t* base = &sB[buf][sub * HTILE];
                #pragma unroll
                for (int sl = 0; sl < 4; sl++) {
                    int p0 = sl * 8 + tg;
                    int p1 = p0 + 4;
                    uint32_t a[2][4];
                    a[0][0] = ((wA0 >> p0) & 1u) * ONE_BF16X2;
                    a[0][1] = ((wA1 >> p0) & 1u) * ONE_BF16X2;
                    a[0][2] = ((wA0 >> p1) & 1u) * ONE_BF16X2;
                    a[0][3] = ((wA1 >> p1) & 1u) * ONE_BF16X2;
                    a[1][0] = ((wA2 >> p0) & 1u) * ONE_BF16X2;
                    a[1][1] = ((wA3 >> p0) & 1u) * ONE_BF16X2;
                    a[1][2] = ((wA2 >> p1) & 1u) * ONE_BF16X2;
                    a[1][3] = ((wA3 >> p1) & 1u) * ONE_BF16X2;

                    #pragma unroll
                    for (int i2 = 0; i2 < 2; i2++) {
                        uint4 bfr = *(const uint4*)(base + sl * 2048 + (wc * 2 + i2) * 512 + lane * 16);
                        #pragma unroll
                        for (int mt = 0; mt < 2; mt++) {
                            mma_bf16(acc[mt][i2 * 2],     a[mt], bfr.x, bfr.y);
                            mma_bf16(acc[mt][i2 * 2 + 1], a[mt], bfr.z, bfr.w);
                        }
                    }
                }
            }

            __syncthreads();
            if (t == 0 && cc + 2 < NCHG / 2) {
                mbar_expect_tx(mb + buf * 8, 2 * HTILE);
                bulk_g2s(sb0 + buf * 2 * HTILE, Bsrc + (size_t)(cc + 2) * 2 * HTILE,
                         2 * HTILE, mb + buf * 8);
            }
        }

        // wait for degree CTAs (all 256 CTAs co-resident -> no deadlock)
        if (t == 0) {
            while (atomicAdd(&g_deg_done, 0) < DEG_CTAS) {}
        }
        __syncthreads();
        __threadfence();

        // epilogue: final = (acc + self) * inv_deg, direct to new_h
        #pragma unroll
        for (int mt = 0; mt < 2; mt++)
            #pragma unroll
            for (int i2 = 0; i2 < 2; i2++)
                #pragma unroll
                for (int fi = 0; fi < 2; fi++)
                    #pragma unroll
                    for (int rr = 0; rr < 4; rr++) {
                        int m = rowbase + mt * 16 + g + ((rr >> 1) ? 8 : 0);
                        int n = hf * 64 + ((wc * 2 + i2) * 2 + fi) * 8 + 2 * tg + (rr & 1);
                        int b = n >> 3, d = n & 7;
                        float v = (acc[mt][i2 * 2 + fi][rr] + g_Ht[m * NC + n]) * g_inv_deg[m];
                        new_h[((size_t)b * NN + m) * ND + d] = v;
                    }
    } else {
        // degree: inv_deg = 1/(popcount(row)+1)
        int wid_g = (bid - MMA_CTAS) * 8 + w;       // 0..1023
        #pragma unroll
        for (int it = 0; it < 8; it++) {
            int row = wid_g + it * 1024;
            const uint32_t* wp = &g_bits[row * WPR];
            int cnt = 0;
            #pragma unroll
            for (int tt = 0; tt < WPR / 32; tt++) cnt += __popc(wp[lane + tt * 32]);
            #pragma unroll
            for (int o = 16; o; o >>= 1) cnt += __shfl_xor_sync(0xffffffffu, cnt, o);
            if (lane == 0) g_inv_deg[row] = 1.0f / (float)(cnt + 1);
        }
        __syncthreads();
        __threadfence();
        if (t == 0) atomicAdd(&g_deg_done, 1);
    }
}

// ---------------- launch ----------------
extern "C" void kernel_launch(void* const* d_in, const int* in_sizes, int n_in,
                              void* d_out, int out_size) {
    const float* h     = (const float*)d_in[0];
    const void*  adj_i = d_in[1];
    const void*  adj_j = d_in[2];
    const float* W     = (const float*)d_in[3];
    const float* bias  = (const float*)d_in[4];
    float* edge_out = (float*)d_out;                                   // (B,E,D)
    float* new_h    = (float*)d_out + (long long)NB * NE * ND;         // (B,N,D)

    k_init<<<2048, 256>>>(adj_i);
    k_pse<<<PSE_CTAS, 256>>>(h, adj_i, adj_j, W, bias, edge_out);
    k_md<<<MMA_CTAS + DEG_CTAS, 256>>>(new_h);
}

// round 15
// speedup vs baseline: 1.0020x; 1.0020x over previous
#include <cuda_runtime.h>
#include <cuda_bf16.h>
#include <stdint.h>

#define NB 16
#define NN 8192
#define NE 262144
#define ND 8
#define NC 128               // NB*ND columns of the transposed H matrix
#define WPR 256              // words per bitmap row = NN/32
#define NCHG 256             // global 32-k chunks
#define HTILE 8192           // per-half per-gc B tile bytes (4 sl x 4 np x 32 lanes x 16B)
#define ONE_BF16X2 0x3F803F80u

// k_pse dispatch
#define TRANS_CTAS 4096      // NN*NC/256
#define MAKEB_CTAS 2048      // 2^19/256
#define PREP_CTAS  (TRANS_CTAS + MAKEB_CTAS)
#define SE_CTAS    32768     // 16384 scatter + 16384 edge, parity-interleaved
#define PSE_CTAS   (PREP_CTAS + SE_CTAS)

// k_md dispatch
#define MMA_CTAS   128       // 64 mtiles x 2 n-halves, full K each
#define DEG_CTAS   128

// ---------------- device scratch (no allocs allowed) ----------------
__device__ uint32_t g_bits[NN * WPR];            // 8 MB adjacency bitmap
__device__ float    g_inv_deg[NN];
__device__ float    g_Ht[NN * NC];               // 4 MB
__device__ uint8_t  g_Bf[2 * NCHG * HTILE];      // 4 MB: [half][gc][8KB tile]
__device__ int      g_is64;
__device__ int      g_deg_done;

// ---------------- PTX helpers ----------------
__device__ __forceinline__ void mbar_init(uint32_t mbar, uint32_t count) {
    asm volatile("mbarrier.init.shared.b64 [%0], %1;" :: "r"(mbar), "r"(count) : "memory");
}
__device__ __forceinline__ void mbar_expect_tx(uint32_t mbar, uint32_t bytes) {
    asm volatile("mbarrier.arrive.expect_tx.shared.b64 _, [%0], %1;"
                 :: "r"(mbar), "r"(bytes) : "memory");
}
__device__ __forceinline__ void bulk_g2s(uint32_t dst, const void* src, uint32_t bytes, uint32_t mbar) {
    asm volatile("cp.async.bulk.shared::cluster.global.mbarrier::complete_tx::bytes [%0], [%1], %2, [%3];"
                 :: "r"(dst), "l"(src), "r"(bytes), "r"(mbar) : "memory");
}
__device__ __forceinline__ void mbar_wait(uint32_t mbar, uint32_t parity) {
    asm volatile(
        "{\n\t.reg .pred P;\n\t"
        "WAIT_%=:\n\t"
        "mbarrier.try_wait.parity.acquire.cta.shared::cta.b64 P, [%0], %1, 0x989680;\n\t"
        "@!P bra WAIT_%=;\n\t}"
        :: "r"(mbar), "r"(parity) : "memory");
}
__device__ __forceinline__ void mma_bf16(float* c, const uint32_t* a, uint32_t b0, uint32_t b1) {
    asm("mma.sync.aligned.m16n8k16.row.col.f32.bf16.bf16.f32 "
        "{%0,%1,%2,%3}, {%4,%5,%6,%7}, {%8,%9}, {%0,%1,%2,%3};"
        : "+f"(c[0]), "+f"(c[1]), "+f"(c[2]), "+f"(c[3])
        : "r"(a[0]), "r"(a[1]), "r"(a[2]), "r"(a[3]), "r"(b0), "r"(b1));
}
__device__ __forceinline__ int load_idx(const void* p, long long e, bool is64) {
    return is64 ? (int)((const long long*)p)[e] : ((const int*)p)[e];
}

// ---------------- init: clear bitmap + detect + reset counter ----------------
__global__ __launch_bounds__(256) void k_init(const void* adj_i) {
    int idx = blockIdx.x * 256 + threadIdx.x;
    ((uint4*)g_bits)[idx] = make_uint4(0u, 0u, 0u, 0u);
    if (idx == 0) {
        const int* p = (const int*)adj_i;
        int odd_nonzero = 0;
        #pragma unroll
        for (int t = 0; t < 32; t++)
            if (p[2 * t + 1] != 0) odd_nonzero = 1;
        g_is64 = odd_nonzero ? 0 : 1;
        g_deg_done = 0;
    }
}

// ---------------- pse: transpose + makeB + scatter + edge (fused) ----------------
__global__ __launch_bounds__(256) void k_pse(
        const float* __restrict__ h,
        const void* adj_i, const void* adj_j,
        const float* __restrict__ W, const float* __restrict__ bias,
        float* __restrict__ edge_out) {
    int bid = blockIdx.x;
    int t   = threadIdx.x;

    if (bid < TRANS_CTAS) {
        int idx = bid * 256 + t;                   // over NN*NC
        int k = idx >> 7;
        int c = idx & 127;
        int b = c >> 3, d = c & 7;
        g_Ht[idx] = h[((long long)b * NN + k) * ND + d];
        return;
    }
    if (bid < PREP_CTAS) {
        int idx = (bid - TRANS_CTAS) * 256 + t;    // 2^19
        int lane = idx & 31;
        int nb   = (idx >> 5) & 15;
        int sl   = (idx >> 9) & 3;
        int gc   = idx >> 11;
        int tg = lane & 3, g = lane >> 2;
        int n  = nb * 8 + g;
        int kb = gc * 32 + sl * 8;
        int b = n >> 3, d = n & 7;
        float v0 = h[((long long)b * NN + (kb + tg)) * ND + d];
        float v1 = h[((long long)b * NN + (kb + 4 + tg)) * ND + d];
        __nv_bfloat16 h0 = __float2bfloat16(v0);
        __nv_bfloat16 l0 = __float2bfloat16(v0 - __bfloat162float(h0));
        __nv_bfloat16 h1 = __float2bfloat16(v1);
        __nv_bfloat16 l1 = __float2bfloat16(v1 - __bfloat162float(h1));
        uint32_t r0 = (uint32_t)__bfloat16_as_ushort(h0) | ((uint32_t)__bfloat16_as_ushort(l0) << 16);
        uint32_t r1 = (uint32_t)__bfloat16_as_ushort(h1) | ((uint32_t)__bfloat16_as_ushort(l1) << 16);
        int half = nb >> 3, nbl = nb & 7;
        uint2* dst = (uint2*)(g_Bf + (size_t)half * (NCHG * HTILE) + (size_t)gc * HTILE
                              + sl * 2048 + (nbl >> 1) * 512 + lane * 16 + (nbl & 1) * 8);
        *dst = make_uint2(r0, r1);
        return;
    }

    int r = bid - PREP_CTAS;
    bool is64 = g_is64;
    if (r & 1) {
        // ---- scatter ----
        long long idx = (long long)(r >> 1) * 256 + t;
        int i = load_idx(adj_i, idx, is64);
        int j = load_idx(adj_j, idx, is64);
        atomicOr(&g_bits[i * WPR + (j >> 5)], 1u << (j & 31));
        atomicOr(&g_bits[j * WPR + (i >> 5)], 1u << (i & 31));
    } else {
        // ---- edge_out ----
        __shared__ float sW[64];
        __shared__ float sb[8];
        if (t < 64) sW[t] = W[t];
        if (t < 8)  sb[t] = bias[t];
        __syncthreads();

        long long idx = (long long)(r >> 1) * 256 + t;
        int bb = (int)(idx >> 18);
        int e  = (int)(idx & (NE - 1));
        int i = load_idx(adj_i, e, is64);   // batch-0 indices only
        int j = load_idx(adj_j, e, is64);

        const float4* h4 = (const float4*)h;
        long long bi = ((long long)bb * NN + i) * 2;
        long long bj = ((long long)bb * NN + j) * 2;
        float4 x0 = h4[bi], x1 = h4[bi + 1];
        float4 y0 = h4[bj], y1 = h4[bj + 1];
        float s[8] = {x0.x + y0.x, x0.y + y0.y, x0.z + y0.z, x0.w + y0.w,
                      x1.x + y1.x, x1.y + y1.y, x1.z + y1.z, x1.w + y1.w};
        float o[8];
        #pragma unroll
        for (int d = 0; d < 8; d++) {
            float a2 = sb[d];
            #pragma unroll
            for (int k = 0; k < 8; k++) a2 += s[k] * sW[d * 8 + k];
            o[d] = a2;
        }
        float4* out4 = (float4*)(edge_out + idx * 8);
        out4[0] = make_float4(o[0], o[1], o[2], o[3]);
        out4[1] = make_float4(o[4], o[5], o[6], o[7]);
    }
}

// ---------------- md: N-split full-K MMA GEMM + degree, fused epilogue ----------------
// bids [0,128):   MMA, CTA = 128 rows x 64 cols (half hf), full K. No partials:
//                 epilogue spin-waits on deg counter, writes final new_h.
// bids [128,256): degree -> inv_deg, then counter arrive.
__global__ __launch_bounds__(256) void k_md(float* __restrict__ new_h) {
    __shared__ __align__(1024) uint8_t sB[2][2 * HTILE];     // 32 KB
    __shared__ __align__(8) unsigned long long smbar[2];

    int bid  = blockIdx.x;
    int t    = threadIdx.x;
    int lane = t & 31;
    int w    = t >> 5;

    if (bid < MMA_CTAS) {
        int wr = w >> 1;                 // m-row 0..3
        int wc = w & 1;                  // n-col 0..1 (32 cols each within the 64-col half)
        int tg = lane & 3, g = lane >> 2;

        int hf    = bid & 1;
        int mtile = bid >> 1;
        int rowbase = mtile * 128 + wr * 32;

        const uint32_t* __restrict__ bits = g_bits;
        const uint8_t*  __restrict__ Bsrc = g_Bf + (size_t)hf * (NCHG * HTILE);

        uint32_t mb  = (uint32_t)__cvta_generic_to_shared(&smbar[0]);
        uint32_t sb0 = (uint32_t)__cvta_generic_to_shared(&sB[0][0]);

        if (t == 0) {
            mbar_init(mb, 1);
            mbar_init(mb + 8, 1);
            asm volatile("fence.proxy.async.shared::cta;" ::: "memory");
        }
        __syncthreads();
        if (t == 0) {
            mbar_expect_tx(mb, 2 * HTILE);
            bulk_g2s(sb0, Bsrc, 2 * HTILE, mb);
            mbar_expect_tx(mb + 8, 2 * HTILE);
            bulk_g2s(sb0 + 2 * HTILE, Bsrc + 2 * HTILE, 2 * HTILE, mb + 8);
        }

        float acc[2][4][4];
        #pragma unroll
        for (int mt = 0; mt < 2; mt++)
            #pragma unroll
            for (int ni = 0; ni < 4; ni++)
                #pragma unroll
                for (int rr = 0; rr < 4; rr++) acc[mt][ni][rr] = 0.0f;

        for (int cc = 0; cc < NCHG / 2; cc++) {      // 128 iters, 2 gc each
            int buf = cc & 1;
            mbar_wait(mb + buf * 8, (cc >> 1) & 1);

            #pragma unroll
            for (int sub = 0; sub < 2; sub++) {
                uint32_t wrd = __ldg(&bits[(rowbase + lane) * WPR + cc * 2 + sub]);
                uint32_t wA0 = __shfl_sync(0xffffffffu, wrd, g);
                uint32_t wA1 = __shfl_sync(0xffffffffu, wrd, g + 8);
                uint32_t wA2 = __shfl_sync(0xffffffffu, wrd, g + 16);
                uint32_t wA3 = __shfl_sync(0xffffffffu, wrd, g + 24);

                const uint8_t* base = &sB[buf][sub * HTILE];
                #pragma unroll
                for (int sl = 0; sl < 4; sl++) {
                    int p0 = sl * 8 + tg;
                    int p1 = p0 + 4;
                    uint32_t a[2][4];
                    a[0][0] = ((wA0 >> p0) & 1u) * ONE_BF16X2;
                    a[0][1] = ((wA1 >> p0) & 1u) * ONE_BF16X2;
                    a[0][2] = ((wA0 >> p1) & 1u) * ONE_BF16X2;
                    a[0][3] = ((wA1 >> p1) & 1u) * ONE_BF16X2;
                    a[1][0] = ((wA2 >> p0) & 1u) * ONE_BF16X2;
                    a[1][1] = ((wA3 >> p0) & 1u) * ONE_BF16X2;
                    a[1][2] = ((wA2 >> p1) & 1u) * ONE_BF16X2;
                    a[1][3] = ((wA3 >> p1) & 1u) * ONE_BF16X2;

                    #pragma unroll
                    for (int i2 = 0; i2 < 2; i2++) {
                        uint4 bfr = *(const uint4*)(base + sl * 2048 + (wc * 2 + i2) * 512 + lane * 16);
                        #pragma unroll
                        for (int mt = 0; mt < 2; mt++) {
                            mma_bf16(acc[mt][i2 * 2],     a[mt], bfr.x, bfr.y);
                            mma_bf16(acc[mt][i2 * 2 + 1], a[mt], bfr.z, bfr.w);
                        }
                    }
                }
            }

            __syncthreads();
            if (t == 0 && cc + 2 < NCHG / 2) {
                mbar_expect_tx(mb + buf * 8, 2 * HTILE);
                bulk_g2s(sb0 + buf * 2 * HTILE, Bsrc + (size_t)(cc + 2) * 2 * HTILE,
                         2 * HTILE, mb + buf * 8);
            }
        }

        // wait for degree CTAs (all 256 CTAs co-resident -> no deadlock)
        if (t == 0) {
            while (atomicAdd(&g_deg_done, 0) < DEG_CTAS) {}
        }
        __syncthreads();
        __threadfence();

        // epilogue: final = (acc + self) * inv_deg, direct to new_h
        #pragma unroll
        for (int mt = 0; mt < 2; mt++)
            #pragma unroll
            for (int i2 = 0; i2 < 2; i2++)
                #pragma unroll
                for (int fi = 0; fi < 2; fi++)
                    #pragma unroll
                    for (int rr = 0; rr < 4; rr++) {
                        int m = rowbase + mt * 16 + g + ((rr >> 1) ? 8 : 0);
                        int n = hf * 64 + ((wc * 2 + i2) * 2 + fi) * 8 + 2 * tg + (rr & 1);
                        int b = n >> 3, d = n & 7;
                        float v = (acc[mt][i2 * 2 + fi][rr] + g_Ht[m * NC + n]) * g_inv_deg[m];
                        new_h[((size_t)b * NN + m) * ND + d] = v;
                    }
    } else {
        // degree: inv_deg = 1/(popcount(row)+1)
        int wid_g = (bid - MMA_CTAS) * 8 + w;       // 0..1023
        #pragma unroll
        for (int it = 0; it < 8; it++) {
            int row = wid_g + it * 1024;
            const uint32_t* wp = &g_bits[row * WPR];
            int cnt = 0;
            #pragma unroll
            for (int tt = 0; tt < WPR / 32; tt++) cnt += __popc(wp[lane + tt * 32]);
            #pragma unroll
            for (int o = 16; o; o >>= 1) cnt += __shfl_xor_sync(0xffffffffu, cnt, o);
            if (lane == 0) g_inv_deg[row] = 1.0f / (float)(cnt + 1);
        }
        __syncthreads();
        __threadfence();
        if (t == 0) atomicAdd(&g_deg_done, 1);
    }
}

// ---------------- launch ----------------
extern "C" void kernel_launch(void* const* d_in, const int* in_sizes, int n_in,
                              void* d_out, int out_size) {
    const float* h     = (const float*)d_in[0];
    const void*  adj_i = d_in[1];
    const void*  adj_j = d_in[2];
    const float* W     = (const float*)d_in[3];
    const float* bias  = (const float*)d_in[4];
    float* edge_out = (float*)d_out;                                   // (B,E,D)
    float* new_h    = (float*)d_out + (long long)NB * NE * ND;         // (B,N,D)

    k_init<<<2048, 256>>>(adj_i);
    k_pse<<<PSE_CTAS, 256>>>(h, adj_i, adj_j, W, bias, edge_out);
    k_md<<<MMA_CTAS + DEG_CTAS, 256>>>(new_h);
}

// round 16
// speedup vs baseline: 1.0038x; 1.0018x over previous
#include <cuda_runtime.h>
#include <cuda_bf16.h>
#include <stdint.h>

#define NB 16
#define NN 8192
#define NE 262144
#define ND 8
#define NC 128               // NB*ND columns of the transposed H matrix
#define WPR 256              // words per bitmap row = NN/32
#define NCHG 256             // global 32-k chunks
#define HTILE 8192           // per-half per-gc B tile bytes (4 sl x 4 np x 32 lanes x 16B)
#define ONE_BF16X2 0x3F803F80u

// k_pse dispatch
#define TRANS_CTAS 4096      // NN*NC/256
#define MAKEB_CTAS 2048      // 2^19/256
#define PREP_CTAS  (TRANS_CTAS + MAKEB_CTAS)
#define SE_CTAS    32768     // 16384 scatter + 16384 edge, parity-interleaved
#define PSE_CTAS   (PREP_CTAS + SE_CTAS)

// k_md dispatch
#define MMA_CTAS   128       // 64 mtiles x 2 n-halves, full K each
#define DEG_CTAS   128

// ---------------- device scratch (no allocs allowed) ----------------
__device__ uint32_t g_bits[NN * WPR];            // 8 MB adjacency bitmap
__device__ float    g_inv_deg[NN];
__device__ float    g_Ht[NN * NC];               // 4 MB
__device__ uint8_t  g_Bf[2 * NCHG * HTILE];      // 4 MB: [half][gc][8KB tile]
__device__ int      g_is64;
__device__ int      g_deg_done;

// ---------------- PTX helpers ----------------
__device__ __forceinline__ void mbar_init(uint32_t mbar, uint32_t count) {
    asm volatile("mbarrier.init.shared.b64 [%0], %1;" :: "r"(mbar), "r"(count) : "memory");
}
__device__ __forceinline__ void mbar_expect_tx(uint32_t mbar, uint32_t bytes) {
    asm volatile("mbarrier.arrive.expect_tx.shared.b64 _, [%0], %1;"
                 :: "r"(mbar), "r"(bytes) : "memory");
}
__device__ __forceinline__ void bulk_g2s(uint32_t dst, const void* src, uint32_t bytes, uint32_t mbar) {
    asm volatile("cp.async.bulk.shared::cluster.global.mbarrier::complete_tx::bytes [%0], [%1], %2, [%3];"
                 :: "r"(dst), "l"(src), "r"(bytes), "r"(mbar) : "memory");
}
__device__ __forceinline__ void mbar_wait(uint32_t mbar, uint32_t parity) {
    asm volatile(
        "{\n\t.reg .pred P;\n\t"
        "WAIT_%=:\n\t"
        "mbarrier.try_wait.parity.acquire.cta.shared::cta.b64 P, [%0], %1, 0x989680;\n\t"
        "@!P bra WAIT_%=;\n\t}"
        :: "r"(mbar), "r"(parity) : "memory");
}
__device__ __forceinline__ void mma_bf16(float* c, const uint32_t* a, uint32_t b0, uint32_t b1) {
    asm("mma.sync.aligned.m16n8k16.row.col.f32.bf16.bf16.f32 "
        "{%0,%1,%2,%3}, {%4,%5,%6,%7}, {%8,%9}, {%0,%1,%2,%3};"
        : "+f"(c[0]), "+f"(c[1]), "+f"(c[2]), "+f"(c[3])
        : "r"(a[0]), "r"(a[1]), "r"(a[2]), "r"(a[3]), "r"(b0), "r"(b1));
}
__device__ __forceinline__ int load_idx(const void* p, long long e, bool is64) {
    return is64 ? (int)((const long long*)p)[e] : ((const int*)p)[e];
}

// ---------------- init: clear bitmap + detect + reset counter ----------------
__global__ __launch_bounds__(256) void k_init(const void* adj_i) {
    int idx = blockIdx.x * 256 + threadIdx.x;
    ((uint4*)g_bits)[idx] = make_uint4(0u, 0u, 0u, 0u);
    if (idx == 0) {
        const int* p = (const int*)adj_i;
        int odd_nonzero = 0;
        #pragma unroll
        for (int t = 0; t < 32; t++)
            if (p[2 * t + 1] != 0) odd_nonzero = 1;
        g_is64 = odd_nonzero ? 0 : 1;
        g_deg_done = 0;
    }
}

// ---------------- pse: transpose + makeB + scatter + edge (fused) ----------------
__global__ __launch_bounds__(256) void k_pse(
        const float* __restrict__ h,
        const void* adj_i, const void* adj_j,
        const float* __restrict__ W, const float* __restrict__ bias,
        float* __restrict__ edge_out) {
    int bid = blockIdx.x;
    int t   = threadIdx.x;

    if (bid < TRANS_CTAS) {
        int idx = bid * 256 + t;                   // over NN*NC
        int k = idx >> 7;
        int c = idx & 127;
        int b = c >> 3, d = c & 7;
        g_Ht[idx] = h[((long long)b * NN + k) * ND + d];
        return;
    }
    if (bid < PREP_CTAS) {
        int idx = (bid - TRANS_CTAS) * 256 + t;    // 2^19
        int lane = idx & 31;
        int nb   = (idx >> 5) & 15;
        int sl   = (idx >> 9) & 3;
        int gc   = idx >> 11;
        int tg = lane & 3, g = lane >> 2;
        int n  = nb * 8 + g;
        int kb = gc * 32 + sl * 8;
        int b = n >> 3, d = n & 7;
        float v0 = h[((long long)b * NN + (kb + tg)) * ND + d];
        float v1 = h[((long long)b * NN + (kb + 4 + tg)) * ND + d];
        __nv_bfloat16 h0 = __float2bfloat16(v0);
        __nv_bfloat16 l0 = __float2bfloat16(v0 - __bfloat162float(h0));
        __nv_bfloat16 h1 = __float2bfloat16(v1);
        __nv_bfloat16 l1 = __float2bfloat16(v1 - __bfloat162float(h1));
        uint32_t r0 = (uint32_t)__bfloat16_as_ushort(h0) | ((uint32_t)__bfloat16_as_ushort(l0) << 16);
        uint32_t r1 = (uint32_t)__bfloat16_as_ushort(h1) | ((uint32_t)__bfloat16_as_ushort(l1) << 16);
        int half = nb >> 3, nbl = nb & 7;
        uint2* dst = (uint2*)(g_Bf + (size_t)half * (NCHG * HTILE) + (size_t)gc * HTILE
                              + sl * 2048 + (nbl >> 1) * 512 + lane * 16 + (nbl & 1) * 8);
        *dst = make_uint2(r0, r1);
        return;
    }

    int r = bid - PREP_CTAS;
    bool is64 = g_is64;
    if (r & 1) {
        // ---- scatter ----
        long long idx = (long long)(r >> 1) * 256 + t;
        int i = load_idx(adj_i, idx, is64);
        int j = load_idx(adj_j, idx, is64);
        atomicOr(&g_bits[i * WPR + (j >> 5)], 1u << (j & 31));
        atomicOr(&g_bits[j * WPR + (i >> 5)], 1u << (i & 31));
    } else {
        // ---- edge_out ----
        __shared__ float sW[64];
        __shared__ float sb[8];
        if (t < 64) sW[t] = W[t];
        if (t < 8)  sb[t] = bias[t];
        __syncthreads();

        long long idx = (long long)(r >> 1) * 256 + t;
        int bb = (int)(idx >> 18);
        int e  = (int)(idx & (NE - 1));
        int i = load_idx(adj_i, e, is64);   // batch-0 indices only
        int j = load_idx(adj_j, e, is64);

        const float4* h4 = (const float4*)h;
        long long bi = ((long long)bb * NN + i) * 2;
        long long bj = ((long long)bb * NN + j) * 2;
        float4 x0 = h4[bi], x1 = h4[bi + 1];
        float4 y0 = h4[bj], y1 = h4[bj + 1];
        float s[8] = {x0.x + y0.x, x0.y + y0.y, x0.z + y0.z, x0.w + y0.w,
                      x1.x + y1.x, x1.y + y1.y, x1.z + y1.z, x1.w + y1.w};
        float o[8];
        #pragma unroll
        for (int d = 0; d < 8; d++) {
            float a2 = sb[d];
            #pragma unroll
            for (int k = 0; k < 8; k++) a2 += s[k] * sW[d * 8 + k];
            o[d] = a2;
        }
        float4* out4 = (float4*)(edge_out + idx * 8);
        out4[0] = make_float4(o[0], o[1], o[2], o[3]);
        out4[1] = make_float4(o[4], o[5], o[6], o[7]);
    }
}

// ---------------- md: N-split full-K MMA GEMM + degree, fused epilogue ----------------
// bids [0,128):   MMA, CTA = 128 rows x 64 cols (half hf), full K. No partials:
//                 epilogue spin-waits on deg counter, writes final new_h.
// bids [128,256): degree -> inv_deg, then counter arrive.
__global__ __launch_bounds__(256) void k_md(float* __restrict__ new_h) {
    __shared__ __align__(1024) uint8_t sB[2][2 * HTILE];     // 32 KB
    __shared__ __align__(8) unsigned long long smbar[2];

    int bid  = blockIdx.x;
    int t    = threadIdx.x;
    int lane = t & 31;
    int w    = t >> 5;

    if (bid < MMA_CTAS) {
        int wr = w >> 1;                 // m-row 0..3
        int wc = w & 1;                  // n-col 0..1 (32 cols each within the 64-col half)
        int tg = lane & 3, g = lane >> 2;

        int hf    = bid & 1;
        int mtile = bid >> 1;
        int rowbase = mtile * 128 + wr * 32;

        const uint32_t* __restrict__ bits = g_bits;
        const uint8_t*  __restrict__ Bsrc = g_Bf + (size_t)hf * (NCHG * HTILE);

        uint32_t mb  = (uint32_t)__cvta_generic_to_shared(&smbar[0]);
        uint32_t sb0 = (uint32_t)__cvta_generic_to_shared(&sB[0][0]);

        if (t == 0) {
            mbar_init(mb, 1);
            mbar_init(mb + 8, 1);
            asm volatile("fence.proxy.async.shared::cta;" ::: "memory");
        }
        __syncthreads();
        if (t == 0) {
            mbar_expect_tx(mb, 2 * HTILE);
            bulk_g2s(sb0, Bsrc, 2 * HTILE, mb);
            mbar_expect_tx(mb + 8, 2 * HTILE);
            bulk_g2s(sb0 + 2 * HTILE, Bsrc + 2 * HTILE, 2 * HTILE, mb + 8);
        }

        float acc[2][4][4];
        #pragma unroll
        for (int mt = 0; mt < 2; mt++)
            #pragma unroll
            for (int ni = 0; ni < 4; ni++)
                #pragma unroll
                for (int rr = 0; rr < 4; rr++) acc[mt][ni][rr] = 0.0f;

        for (int cc = 0; cc < NCHG / 2; cc++) {      // 128 iters, 2 gc each
            int buf = cc & 1;
            mbar_wait(mb + buf * 8, (cc >> 1) & 1);

            #pragma unroll
            for (int sub = 0; sub < 2; sub++) {
                uint32_t wrd = __ldg(&bits[(rowbase + lane) * WPR + cc * 2 + sub]);
                uint32_t wA0 = __shfl_sync(0xffffffffu, wrd, g);
                uint32_t wA1 = __shfl_sync(0xffffffffu, wrd, g + 8);
                uint32_t wA2 = __shfl_sync(0xffffffffu, wrd, g + 16);
                uint32_t wA3 = __shfl_sync(0xffffffffu, wrd, g + 24);

                const uint8_t* base = &sB[buf][sub * HTILE];
                #pragma unroll
                for (int sl = 0; sl < 4; sl++) {
                    int p0 = sl * 8 + tg;
                    int p1 = p0 + 4;
                    uint32_t a[2][4];
                    a[0][0] = ((wA0 >> p0) & 1u) * ONE_BF16X2;
                    a[0][1] = ((wA1 >> p0) & 1u) * ONE_BF16X2;
                    a[0][2] = ((wA0 >> p1) & 1u) * ONE_BF16X2;
                    a[0][3] = ((wA1 >> p1) & 1u) * ONE_BF16X2;
                    a[1][0] = ((wA2 >> p0) & 1u) * ONE_BF16X2;
                    a[1][1] = ((wA3 >> p0) & 1u) * ONE_BF16X2;
                    a[1][2] = ((wA2 >> p1) & 1u) * ONE_BF16X2;
                    a[1][3] = ((wA3 >> p1) & 1u) * ONE_BF16X2;

                    #pragma unroll
                    for (int i2 = 0; i2 < 2; i2++) {
                        uint4 bfr = *(const uint4*)(base + sl * 2048 + (wc * 2 + i2) * 512 + lane * 16);
                        #pragma unroll
                        for (int mt = 0; mt < 2; mt++) {
                            mma_bf16(acc[mt][i2 * 2],     a[mt], bfr.x, bfr.y);
                            mma_bf16(acc[mt][i2 * 2 + 1], a[mt], bfr.z, bfr.w);
                        }
                    }
                }
            }

            __syncthreads();
            if (t == 0 && cc + 2 < NCHG / 2) {
                mbar_expect_tx(mb + buf * 8, 2 * HTILE);
                bulk_g2s(sb0 + buf * 2 * HTILE, Bsrc + (size_t)(cc + 2) * 2 * HTILE,
                         2 * HTILE, mb + buf * 8);
            }
        }

        // wait for degree CTAs (all 256 CTAs co-resident -> no deadlock)
        if (t == 0) {
            while (atomicAdd(&g_deg_done, 0) < DEG_CTAS) {}
        }
        __syncthreads();
        __threadfence();

        // epilogue: final = (acc + self) * inv_deg, direct to new_h
        #pragma unroll
        for (int mt = 0; mt < 2; mt++)
            #pragma unroll
            for (int i2 = 0; i2 < 2; i2++)
                #pragma unroll
                for (int fi = 0; fi < 2; fi++)
                    #pragma unroll
                    for (int rr = 0; rr < 4; rr++) {
                        int m = rowbase + mt * 16 + g + ((rr >> 1) ? 8 : 0);
                        int n = hf * 64 + ((wc * 2 + i2) * 2 + fi) * 8 + 2 * tg + (rr & 1);
                        int b = n >> 3, d = n & 7;
                        float v = (acc[mt][i2 * 2 + fi][rr] + g_Ht[m * NC + n]) * g_inv_deg[m];
                        new_h[((size_t)b * NN + m) * ND + d] = v;
                    }
    } else {
        // degree: inv_deg = 1/(popcount(row)+1)
        int wid_g = (bid - MMA_CTAS) * 8 + w;       // 0..1023
        #pragma unroll
        for (int it = 0; it < 8; it++) {
            int row = wid_g + it * 1024;
            const uint32_t* wp = &g_bits[row * WPR];
            int cnt = 0;
            #pragma unroll
            for (int tt = 0; tt < WPR / 32; tt++) cnt += __popc(wp[lane + tt * 32]);
            #pragma unroll
            for (int o = 16; o; o >>= 1) cnt += __shfl_xor_sync(0xffffffffu, cnt, o);
            if (lane == 0) g_inv_deg[row] = 1.0f / (float)(cnt + 1);
        }
        __syncthreads();
        __threadfence();
        if (t == 0) atomicAdd(&g_deg_done, 1);
    }
}

// ---------------- launch ----------------
extern "C" void kernel_launch(void* const* d_in, const int* in_sizes, int n_in,
                              void* d_out, int out_size) {
    const float* h     = (const float*)d_in[0];
    const void*  adj_i = d_in[1];
    const void*  adj_j = d_in[2];
    const float* W     = (const float*)d_in[3];
    const float* bias  = (const float*)d_in[4];
    float* edge_out = (float*)d_out;                                   // (B,E,D)
    float* new_h    = (float*)d_out + (long long)NB * NE * ND;         // (B,N,D)

    k_init<<<2048, 256>>>(adj_i);
    k_pse<<<PSE_CTAS, 256>>>(h, adj_i, adj_j, W, bias, edge_out);
    k_md<<<MMA_CTAS + DEG_CTAS, 256>>>(new_h);
}